// round 14
// baseline (speedup 1.0000x reference)
#include <cuda_runtime.h>
#include <math.h>

#define G 8192
#define S 64
#define D 128
#define H 256
#define EPS 0.01f

// Output layout: rep [G*D] | mixture [G*8] | scale [G] | alpha [G] | beta [G]
#define O_REP   0
#define O_MIX   (G * D)
#define O_SCALE (O_MIX + G * 8)
#define O_ALPHA (O_SCALE + G)
#define O_BETA  (O_ALPHA + G)

#define CGROUPS 16               // groups per MLP block
#define NCONS (G / CGROUPS)      // 512 MLP blocks

__device__ __forceinline__ float softplus_f(float v) {
    return fmaxf(v, 0.f) + log1pf(expf(-fabsf(v)));
}

__device__ __forceinline__ unsigned long long pack2(float lo, float hi) {
    unsigned long long r;
    asm("mov.b64 %0, {%1, %2};" : "=l"(r) : "f"(lo), "f"(hi));
    return r;
}
__device__ __forceinline__ void unpack2(unsigned long long v, float& lo, float& hi) {
    asm("mov.b64 {%0, %1}, %2;" : "=f"(lo), "=f"(hi) : "l"(v));
}
__device__ __forceinline__ void fma2(unsigned long long& d,
                                     unsigned long long a, unsigned long long b) {
    asm("fma.rn.f32x2 %0, %1, %2, %0;" : "+l"(d) : "l"(a), "l"(b));
}

// ---------------------------------------------------------------------------
// Kernel 1: per-group statistics -> rep. EXACT R3 body (proven ~49us,
// 40 regs, high occupancy — do not touch).
// ---------------------------------------------------------------------------
__global__ __launch_bounds__(256) void stats_kernel(
    const float* __restrict__ x, const float* __restrict__ y,
    const float* __restrict__ ax, const float* __restrict__ ay,
    float* __restrict__ rep)
{
    const int warp = threadIdx.x >> 5;
    const int lane = threadIdx.x & 31;
    const int g = blockIdx.x * 8 + warp;

    const float4* xg = reinterpret_cast<const float4*>(x + (size_t)g * S * D) + lane;
    const float4  a4 = reinterpret_cast<const float4*>(ax + (size_t)g * D)[lane];
    const float   ayv = ay[g];
    const float*  yg = y + (size_t)g * S;

    float sx0 = 0.f, sx1 = 0.f, sx2 = 0.f, sx3 = 0.f;
    float sp0 = 0.f, sp1 = 0.f, sp2 = 0.f, sp3 = 0.f;
    float sxx = 0.f, sy = 0.f;

#pragma unroll 4
    for (int s = 0; s < S; ++s) {
        float4 xv = xg[s * 32];
        float  yv = __ldg(yg + s);
        float xr0 = xv.x - a4.x;
        float xr1 = xv.y - a4.y;
        float xr2 = xv.z - a4.z;
        float xr3 = xv.w - a4.w;
        float yr  = yv - ayv;
        sx0 += xr0; sx1 += xr1; sx2 += xr2; sx3 += xr3;
        sp0 += xr0 * yr; sp1 += xr1 * yr; sp2 += xr2 * yr; sp3 += xr3 * yr;
        sxx += xr0 * xr0 + xr1 * xr1 + xr2 * xr2 + xr3 * xr3;
        sy  += yr;
    }

    float tot = sx0 + sx1 + sx2 + sx3;
    float sxxT = sxx;
#pragma unroll
    for (int o = 16; o > 0; o >>= 1) {
        tot  += __shfl_xor_sync(0xffffffffu, tot,  o);
        sxxT += __shfl_xor_sync(0xffffffffu, sxxT, o);
    }

    const float nD = (float)(S * D);
    const float var = (sxxT - tot * tot / nD) / (nD - 1.f);
    const float inv = 1.f / var;
    const float invn  = 1.f / (float)S;
    const float invn1 = 1.f / (float)(S - 1);

    float4 r;
    r.x = (sp0 - sx0 * sy * invn) * invn1 * inv;
    r.y = (sp1 - sx1 * sy * invn) * invn1 * inv;
    r.z = (sp2 - sx2 * sy * invn) * invn1 * inv;
    r.w = (sp3 - sx3 * sy * invn) * invn1 * inv;
    reinterpret_cast<float4*>(rep + (size_t)g * D)[lane] = r;
}

// ---------------------------------------------------------------------------
// Kernel 2: MLP head = R12 consumer body, standalone. 512 blocks x 256.
// Block = 16 groups. GEMM1 via f32x2 packed FMA, W1 direct from L2.
// Thread = rows [4*rg, 4*rg+4) x cols [c0, c0+4).
// ---------------------------------------------------------------------------
__global__ __launch_bounds__(256) void mlp_kernel(
    const float* __restrict__ rep, const float* __restrict__ W1,
    const float* __restrict__ b1, const float* __restrict__ W2,
    const float* __restrict__ b2, float* __restrict__ out)
{
    __shared__ float sA[CGROUPS * D];   // 8 KB
    __shared__ float sH[CGROUPS * H];   // 16 KB
    __shared__ float sW2[H * 10];       // 10 KB

    const int t = threadIdx.x;
    const int m = blockIdx.x;           // groups [16m, 16m+16)
    const int warp = t >> 5;
    const int lane = t & 31;

    for (int i = t; i < H * 10; i += 256) sW2[i] = W2[i];

    // load A tile (16 rows x 128) : 512 float4
    {
        const float4* src = reinterpret_cast<const float4*>(rep + (size_t)m * CGROUPS * D);
        float4* dst = reinterpret_cast<float4*>(sA);
        dst[t] = src[t];
        dst[t + 256] = src[t + 256];
    }
    __syncthreads();

    // ---- GEMM1 + tanh ----
    {
        const int rg = t >> 6;            // 0..3
        const int c0 = (t & 63) * 4;
        const float* Ab = sA + rg * 4 * D;
        const float4* W1v = reinterpret_cast<const float4*>(W1) + (c0 >> 2);

        unsigned long long acc[4][2];
#pragma unroll
        for (int r = 0; r < 4; ++r) { acc[r][0] = pack2(0.f, 0.f); acc[r][1] = pack2(0.f, 0.f); }

#pragma unroll 8
        for (int k = 0; k < D; ++k) {
            float4 w = W1v[k * (H / 4)];
            unsigned long long wp0 = pack2(w.x, w.y);
            unsigned long long wp1 = pack2(w.z, w.w);
#pragma unroll
            for (int r = 0; r < 4; ++r) {
                float a = Ab[r * D + k];
                unsigned long long ap = pack2(a, a);
                fma2(acc[r][0], ap, wp0);
                fma2(acc[r][1], ap, wp1);
            }
        }

        float4 bb = reinterpret_cast<const float4*>(b1)[c0 >> 2];
#pragma unroll
        for (int r = 0; r < 4; ++r) {
            float v0, v1, v2, v3;
            unpack2(acc[r][0], v0, v1);
            unpack2(acc[r][1], v2, v3);
            float4 h;
            h.x = tanhf(v0 + bb.x);
            h.y = tanhf(v1 + bb.y);
            h.z = tanhf(v2 + bb.z);
            h.w = tanhf(v3 + bb.w);
            *reinterpret_cast<float4*>(sH + (rg * 4 + r) * H + c0) = h;
        }
    }
    __syncthreads();

    // ---- GEMM2 + epilogue: warp handles groups {2*warp, 2*warp+1} ----
#pragma unroll
    for (int i = 0; i < 2; ++i) {
        const int row = warp * 2 + i;
        const float* hrow = sH + row * H;

        float p[10];
#pragma unroll
        for (int k = 0; k < 10; ++k) p[k] = 0.f;

#pragma unroll
        for (int j = 0; j < 8; ++j) {
            float hv = hrow[lane + 32 * j];
            const float* w2r = sW2 + (lane + 32 * j) * 10;
#pragma unroll
            for (int k = 0; k < 10; ++k) p[k] += hv * w2r[k];
        }
#pragma unroll
        for (int k = 0; k < 10; ++k) {
#pragma unroll
            for (int o = 16; o > 0; o >>= 1)
                p[k] += __shfl_xor_sync(0xffffffffu, p[k], o);
        }

        if (lane == 0) {
            const int g = m * CGROUPS + row;
            float o0 = p[0] + __ldg(b2 + 0);
            float o1 = p[1] + __ldg(b2 + 1);
            float alpha = softplus_f(o0) * (1.f - EPS) + EPS;
            float beta  = softplus_f(o1) * (1.f - EPS) + EPS;

            float lg[8];
            float mx = -3.4e38f;
#pragma unroll
            for (int k = 0; k < 8; ++k) {
                lg[k] = p[2 + k] + __ldg(b2 + 2 + k);
                mx = fmaxf(mx, lg[k]);
            }
            float se = 0.f;
#pragma unroll
            for (int k = 0; k < 8; ++k) { lg[k] = expf(lg[k] - mx); se += lg[k]; }
            float inv_se = 1.f / se;
#pragma unroll
            for (int k = 0; k < 8; ++k) out[O_MIX + (size_t)g * 8 + k] = lg[k] * inv_se;

            out[O_SCALE + g] = sqrtf(beta / alpha);
            out[O_ALPHA + g] = alpha;
            out[O_BETA  + g] = beta;
        }
    }
}

// ---------------------------------------------------------------------------
extern "C" void kernel_launch(void* const* d_in, const int* in_sizes, int n_in,
                              void* d_out, int out_size)
{
    (void)in_sizes; (void)n_in; (void)out_size;
    // inputs: 0=index(int32), 1=x, 2=y, 3=anchor_x, 4=anchor_y, 5=W1, 6=b1, 7=W2, 8=b2
    const float* x  = (const float*)d_in[1];
    const float* y  = (const float*)d_in[2];
    const float* ax = (const float*)d_in[3];
    const float* ay = (const float*)d_in[4];
    const float* W1 = (const float*)d_in[5];
    const float* b1 = (const float*)d_in[6];
    const float* W2 = (const float*)d_in[7];
    const float* b2 = (const float*)d_in[8];
    float* out = (float*)d_out;

    stats_kernel<<<G / 8, 256>>>(x, y, ax, ay, out + O_REP);
    mlp_kernel<<<NCONS, 256>>>(out + O_REP, W1, b1, W2, b2, out);
}